// round 12
// baseline (speedup 1.0000x reference)
#include <cuda_runtime.h>
#include <cuda_bf16.h>
#include <stdint.h>
#include <math.h>

#define F_ 4
#define V_ 4
#define E_ 64
#define NIN_ 1024
#define N_ 1024
#define M_ 1026
#define FV_ 16
#define NT_ 16     // k5 n-tiles of 64
#define NT2_ 8     // ksp n-tiles of 128

// ---------------- scratch (all zero-init; k6 restores zeros each replay) ----------------
__device__ unsigned int g_gmax_not[N_];   // max(~bits(gi)) => gmin = ~max
__device__ float g_sumabs[N_];
__device__ int   g_actsel[N_];
__device__ int   g_bsel[M_];
__device__ float g_AN[FV_*E_*M_];
__device__ float g_AAf[F_*M_];
__device__ float g_BBf[F_*M_];
__device__ float g_gneg[F_*M_];
__device__ int   g_negflag[F_*NT2_];
__device__ int   g_anyneg;
__device__ double g_powAB;
__device__ double g_cross;

__device__ __forceinline__ float clampf(float x, float lo, float hi){
    return fminf(fmaxf(x, lo), hi);
}
__device__ __forceinline__ float gmin_of(int n){
    return __uint_as_float(~g_gmax_not[n]);
}
__device__ __forceinline__ uint16_t b1(float a){
    __nv_bfloat16 p = __float2bfloat16(a);
    return *reinterpret_cast<uint16_t*>(&p);
}
__device__ __forceinline__ uint32_t bpack(float a, float b){
    __nv_bfloat162 p = __floats2bfloat162_rn(a, b);
    return *reinterpret_cast<uint32_t*>(&p);
}
__device__ __forceinline__ void mma_bf16(float* d, uint32_t a0, uint32_t a1, uint32_t a2, uint32_t a3,
                                         uint32_t b0, uint32_t b1v){
    asm volatile("mma.sync.aligned.m16n8k16.row.col.f32.bf16.bf16.f32 "
        "{%0,%1,%2,%3}, {%4,%5,%6,%7}, {%8,%9}, {%0,%1,%2,%3};"
        : "+f"(d[0]), "+f"(d[1]), "+f"(d[2]), "+f"(d[3])
        : "r"(a0), "r"(a1), "r"(a2), "r"(a3), "r"(b0), "r"(b1v));
}

// ---------------- K1: theta column min/sum + gumbel selections ----------------
__global__ void k1_theta(const float* __restrict__ theta_,
                         const float* __restrict__ coeff_act,
                         const float* __restrict__ coeff_neg,
                         const float* __restrict__ gum_act,
                         const float* __restrict__ gum_neg)
{
    int n  = blockIdx.x*256 + threadIdx.x;
    int m0 = blockIdx.y*57;
    float lmin = 3.4e38f, lsum = 0.f;
    #pragma unroll 3
    for (int r=0; r<57; r++){
        int m = m0 + r;
        float gi = fabsf(clampf(theta_[m*N_ + n], -1.f, 1.f));
        lmin = fminf(lmin, gi);
        lsum += gi;
    }
    atomicMax(&g_gmax_not[n], ~__float_as_uint(lmin));
    atomicAdd(&g_sumabs[n], lsum);

    if (blockIdx.y == 0){
        float v0 = clampf(coeff_act[n],    -1.f, 1.f) + gum_act[n];
        float v1 = clampf(coeff_act[N_+n], -1.f, 1.f) + gum_act[N_+n];
        g_actsel[n] = (v1 > v0) ? 1 : 0;
    } else if (blockIdx.y == 1){
        float v0 = clampf(coeff_neg[n],    -1.f, 1.f) + gum_neg[n];
        float v1 = clampf(coeff_neg[M_+n], -1.f, 1.f) + gum_neg[M_+n];
        g_bsel[n] = (v1 > v0) ? 1 : 0;
    } else if (blockIdx.y == 2){
        int m = 1024 + n;
        if (m < M_){
            float v0 = clampf(coeff_neg[m],    -1.f, 1.f) + gum_neg[m];
            float v1 = clampf(coeff_neg[M_+m], -1.f, 1.f) + gum_neg[M_+m];
            g_bsel[m] = (v1 > v0) ? 1 : 0;
        }
    }
}

// ---------------- K3a: AAf (320 blocks) ----------------
__global__ void k3a_AA(const float* __restrict__ a)
{
    int fv = blockIdx.x, f = fv >> 2;
    int m  = blockIdx.y*256 + threadIdx.x;
    int es = blockIdx.z;
    if (m >= M_) return;
    float AA = 0.f;
    #pragma unroll 4
    for (int r = 0; r < 16; r++){
        int e = es*16 + r;
        float ax = (m < NIN_) ? a[(size_t)(fv*E_+e)*NIN_ + m] : ((m == NIN_) ? 1.f : 0.f);
        AA += ax*ax;
    }
    atomicAdd(&g_AAf[f*M_ + m], AA);
}

// ---------------- KSP: neg flags + pos powAB + gneg ----------------
__global__ __launch_bounds__(256) void ksp(const float* __restrict__ theta_,
                                           const float* __restrict__ fault)
{
    int f  = blockIdx.x;
    int nt = blockIdx.y;
    int mc = blockIdx.z;
    int n  = nt*128 + (threadIdx.x & 127);
    int ms = threadIdx.x >> 7;
    float ginv = 0.1f / gmin_of(n);
    int neg = 0;
    double pab = 0.0;
    #pragma unroll 3
    for (int r=0; r<57; r++){
        int m = mc*114 + r*2 + ms;
        float tc = clampf(theta_[m*N_ + n], -1.f, 1.f);
        float gi = fabsf(tc);
        float th = (gi < 0.01f) ? 0.f : tc;
        float fa = fault[(f*M_ + m)*N_ + n];
        float g  = gi * ginv;
        float s  = th*fa;
        if (s < 0.f){ neg = 1; atomicAdd(&g_gneg[f*M_ + m], g); }
        else        { pab += (double)(g * g_AAf[f*M_ + m]); }
    }
    if (neg){ atomicOr(&g_negflag[f*NT2_ + nt], 1); atomicOr(&g_anyneg, 1); }
    __shared__ double sred[256];
    sred[threadIdx.x] = pab;
    __syncthreads();
    for (int s=128; s>0; s>>=1){
        if (threadIdx.x < s) sred[threadIdx.x] += sred[threadIdx.x+s];
        __syncthreads();
    }
    if (threadIdx.x == 0) atomicAdd(&g_powAB, sred[0]);
}

// ---------------- K3b: an/BBf (only if any neg; early-exit) ----------------
__global__ void k3b_an(const float* __restrict__ a)
{
    if (g_anyneg == 0) return;
    int fv = blockIdx.x;
    int m  = blockIdx.y*256 + threadIdx.x;
    int es = blockIdx.z;
    if (m >= M_) return;
    int bs = g_bsel[m];
    float BB = 0.f;
    #pragma unroll
    for (int r=0; r<8; r++){
        int e = es*8 + r;
        float ax = (m < NIN_) ? a[(size_t)(fv*E_+e)*NIN_ + m] : ((m == NIN_) ? 1.f : 0.f);
        float an;
        if (m == M_-1) an = 0.f;
        else           an = bs ? (1.f/(1.f + expf(4.f*ax - 2.f))) : (1.f - ax);
        g_AN[(size_t)(fv*E_+e)*M_ + m] = an;
        BB += an*an;
    }
    int f = fv >> 2;
    atomicAdd(&g_BBf[f*M_ + m], BB);
}

// ---------------- K5 slim: no-negatives fast path, 3 blocks/SM ----------------
__global__ __launch_bounds__(256, 3) void k5_slim(const float* __restrict__ a,
                                                  const float* __restrict__ theta_,
                                                  const float* __restrict__ noise,
                                                  const float* __restrict__ fault,
                                                  float* __restrict__ out)
{
    if (g_anyneg != 0) return;
    const int fv = blockIdx.x, f = fv >> 2;
    const int n0 = blockIdx.y * 64;
    const int tid = threadIdx.x;
    const int lane = tid & 31, w = tid >> 5;

    __shared__ uint16_t Wt[64][22], Gt[64][22];
    __shared__ uint16_t axs[64][22];
    __shared__ float dsum_s[4][64];
    __shared__ float invd_s[64];
    __shared__ double sred[256];

    const int sn = tid & 63, kq = tid >> 6;   // W/G staging
    const int sk = tid & 15, se = tid >> 4;   // ax staging
    const int g = lane >> 2, t4 = lane & 3;
    const int nw = (w & 3) * 16, ec0 = (w >> 2) * 32;

    const float ginv = 0.1f / gmin_of(n0 + sn);
    float dsum = 0.f;
    float zacc[4][4], z2acc[4][4];
    #pragma unroll
    for (int c=0;c<4;c++)
        #pragma unroll
        for (int q=0;q<4;q++){ zacc[c][q]=0.f; z2acc[c][q]=0.f; }

    float th[4], no[4], fa[4], av[4];

    #pragma unroll
    for (int j=0;j<4;j++){
        int m = kq*4 + j;
        th[j] = theta_[m*N_ + n0+sn];
        no[j] = noise[((size_t)(fv*M_ + m))*N_ + n0+sn];
        fa[j] = fault[((size_t)(f*M_ + m))*N_ + n0+sn];
    }
    #pragma unroll
    for (int r=0;r<4;r++)
        av[r] = a[(size_t)(fv*E_ + se + r*16)*NIN_ + sk];

    for (int t = 0; t < 65; t++){
        __syncthreads();
        // ---- stage current tile from regs ----
        {
            float wv[4], gv[4];
            #pragma unroll
            for (int j=0;j<4;j++){
                float tc = clampf(th[j], -1.f, 1.f);
                float gi = fabsf(tc);
                float thv = (gi < 0.01f) ? 0.f : tc;
                float gt = gi * ginv;
                float tn = thv*(0.9f + 0.2f*no[j])*fa[j];
                wv[j] = fabsf(tn);
                gv[j] = gt;
                dsum += wv[j];
            }
            *(uint32_t*)&Wt[sn][kq*4]   = bpack(wv[0], wv[1]);
            *(uint32_t*)&Wt[sn][kq*4+2] = bpack(wv[2], wv[3]);
            *(uint32_t*)&Gt[sn][kq*4]   = bpack(gv[0], gv[1]);
            *(uint32_t*)&Gt[sn][kq*4+2] = bpack(gv[2], gv[3]);
            #pragma unroll
            for (int r=0;r<4;r++)
                axs[se + r*16][sk] = b1(av[r]);
        }
        // ---- prefetch t+1 ----
        if (t < 64){
            #pragma unroll
            for (int j=0;j<4;j++){
                int m = (t+1)*16 + kq*4 + j;
                if (m < M_){
                    th[j] = theta_[m*N_ + n0+sn];
                    no[j] = noise[((size_t)(fv*M_ + m))*N_ + n0+sn];
                    fa[j] = fault[((size_t)(f*M_ + m))*N_ + n0+sn];
                } else { th[j]=0.f; no[j]=0.f; fa[j]=0.f; }
            }
            #pragma unroll
            for (int r=0;r<4;r++){
                int m = (t+1)*16 + sk;
                av[r] = (m < NIN_) ? a[(size_t)(fv*E_ + se + r*16)*NIN_ + m]
                                   : ((m == NIN_) ? 1.f : 0.f);
            }
        }
        __syncthreads();
        // ---- mma ----
        {
            uint32_t aw0 = *(const uint32_t*)&Wt[nw+g  ][2*t4];
            uint32_t aw1 = *(const uint32_t*)&Wt[nw+g+8][2*t4];
            uint32_t aw2 = *(const uint32_t*)&Wt[nw+g  ][2*t4+8];
            uint32_t aw3 = *(const uint32_t*)&Wt[nw+g+8][2*t4+8];
            uint32_t ag0 = *(const uint32_t*)&Gt[nw+g  ][2*t4];
            uint32_t ag1 = *(const uint32_t*)&Gt[nw+g+8][2*t4];
            uint32_t ag2 = *(const uint32_t*)&Gt[nw+g  ][2*t4+8];
            uint32_t ag3 = *(const uint32_t*)&Gt[nw+g+8][2*t4+8];
            #pragma unroll
            for (int c=0;c<4;c++){
                int e = ec0 + c*8 + g;
                uint32_t b0  = *(const uint32_t*)&axs[e][2*t4];
                uint32_t bb1 = *(const uint32_t*)&axs[e][2*t4+8];
                mma_bf16(zacc[c],  aw0, aw1, aw2, aw3, b0, bb1);
                mma_bf16(z2acc[c], ag0, ag1, ag2, ag3, b0, bb1);
            }
        }
    }

    // ---- D reduction ----
    dsum_s[kq][sn] = dsum;
    __syncthreads();
    if (tid < 64)
        invd_s[tid] = 1.f/(dsum_s[0][tid]+dsum_s[1][tid]+dsum_s[2][tid]+dsum_s[3][tid] + 1e-10f);
    __syncthreads();

    // ---- epilogue ----
    const int r0 = nw + g, r1 = nw + g + 8;
    const float invd0 = invd_s[r0], invd1 = invd_s[r1];
    const float gs0 = g_sumabs[n0+r0] * (0.1f / gmin_of(n0+r0));
    const float gs1 = g_sumabs[n0+r1] * (0.1f / gmin_of(n0+r1));
    const int as0 = g_actsel[n0+r0], as1 = g_actsel[n0+r1];
    double cp = 0.0;
    #pragma unroll
    for (int c=0;c<4;c++){
        int e0 = ec0 + c*8 + 2*t4;
        float vals[4] = { zacc[c][0], zacc[c][1], zacc[c][2], zacc[c][3] };
        float v2[4]   = { z2acc[c][0], z2acc[c][1], z2acc[c][2], z2acc[c][3] };
        #pragma unroll
        for (int q=0;q<4;q++){
            int e  = e0 + (q & 1);
            int rr = (q < 2) ? r0 : r1;
            float invd = (q < 2) ? invd0 : invd1;
            float gsn  = (q < 2) ? gs0 : gs1;
            int   asel = (q < 2) ? as0 : as1;
            float zz = vals[q] * invd;
            float act = asel ? tanhf(zz) : (1.f/(1.f + expf(2.f - 4.f*zz)));
            out[(size_t)(fv*E_ + e)*N_ + n0 + rr] = act;
            cp += (double)zz * ((double)gsn*(double)zz - 2.0*(double)v2[q]);
        }
    }
    sred[tid] = cp;
    __syncthreads();
    for (int s=128; s>0; s>>=1){
        if (tid < s) sred[tid] += sred[tid+s];
        __syncthreads();
    }
    if (tid == 0) atomicAdd(&g_cross, sred[0]);
}

// ---------------- K5 full: general path (R6-proven), gated on anyneg ----------------
__global__ __launch_bounds__(256, 2) void k5_full(const float* __restrict__ a,
                                                  const float* __restrict__ theta_,
                                                  const float* __restrict__ noise,
                                                  const float* __restrict__ fault,
                                                  float* __restrict__ out)
{
    if (g_anyneg == 0) return;
    const int fv = blockIdx.x, f = fv >> 2;
    const int n0 = blockIdx.y * 64;
    const int tid = threadIdx.x;
    const int lane = tid & 31, w = tid >> 5;
    const bool anyneg = (g_negflag[f*NT2_ + (blockIdx.y >> 1)] != 0);

    __shared__ uint16_t Wt[64][20], Gt[64][20], Wq[64][20], Gq[64][20];
    __shared__ uint16_t axs[64][20], ans[64][20];
    __shared__ float dsum_s[4][64];
    __shared__ float invd_s[64];
    __shared__ double sred[256];

    const int sn = tid & 63, kq = tid >> 6;
    const int sk = tid & 15, se = tid >> 4;
    const int g = lane >> 2, t4 = lane & 3;
    const int nw = (w & 3) * 16, ec0 = (w >> 2) * 32;

    const float ginv = 0.1f / gmin_of(n0 + sn);
    float dsum = 0.f;
    float zacc[4][4], z2acc[4][4];
    #pragma unroll
    for (int c=0;c<4;c++)
        #pragma unroll
        for (int q=0;q<4;q++){ zacc[c][q]=0.f; z2acc[c][q]=0.f; }

    float th[4], no[4], fa[4], av[4], anv[4];

    #pragma unroll
    for (int j=0;j<4;j++){
        int m = kq*4 + j;
        th[j] = theta_[m*N_ + n0+sn];
        no[j] = noise[((size_t)(fv*M_ + m))*N_ + n0+sn];
        fa[j] = fault[((size_t)(f*M_ + m))*N_ + n0+sn];
    }
    #pragma unroll
    for (int r=0;r<4;r++){
        av[r] = a[(size_t)(fv*E_ + se + r*16)*NIN_ + sk];
        anv[r] = anyneg ? g_AN[(size_t)(fv*E_ + se + r*16)*M_ + sk] : 0.f;
    }

    for (int t = 0; t < 65; t++){
        __syncthreads();
        {
            float wv[4], gv[4]; bool pv[4];
            #pragma unroll
            for (int j=0;j<4;j++){
                float tc = clampf(th[j], -1.f, 1.f);
                float gi = fabsf(tc);
                float thv = (gi < 0.01f) ? 0.f : tc;
                float gt = gi * ginv;
                float tn = thv*(0.9f + 0.2f*no[j])*fa[j];
                wv[j] = fabsf(tn);
                gv[j] = gt;
                pv[j] = (tn >= 0.f);
                dsum += wv[j];
            }
            if (!anyneg){
                *(uint32_t*)&Wt[sn][kq*4]   = bpack(wv[0], wv[1]);
                *(uint32_t*)&Wt[sn][kq*4+2] = bpack(wv[2], wv[3]);
                *(uint32_t*)&Gt[sn][kq*4]   = bpack(gv[0], gv[1]);
                *(uint32_t*)&Gt[sn][kq*4+2] = bpack(gv[2], gv[3]);
            } else {
                *(uint32_t*)&Wt[sn][kq*4]   = bpack(pv[0]?wv[0]:0.f, pv[1]?wv[1]:0.f);
                *(uint32_t*)&Wt[sn][kq*4+2] = bpack(pv[2]?wv[2]:0.f, pv[3]?wv[3]:0.f);
                *(uint32_t*)&Wq[sn][kq*4]   = bpack(pv[0]?0.f:wv[0], pv[1]?0.f:wv[1]);
                *(uint32_t*)&Wq[sn][kq*4+2] = bpack(pv[2]?0.f:wv[2], pv[3]?0.f:wv[3]);
                *(uint32_t*)&Gt[sn][kq*4]   = bpack(pv[0]?gv[0]:0.f, pv[1]?gv[1]:0.f);
                *(uint32_t*)&Gt[sn][kq*4+2] = bpack(pv[2]?gv[2]:0.f, pv[3]?gv[3]:0.f);
                *(uint32_t*)&Gq[sn][kq*4]   = bpack(pv[0]?0.f:gv[0], pv[1]?0.f:gv[1]);
                *(uint32_t*)&Gq[sn][kq*4+2] = bpack(pv[2]?0.f:gv[2], pv[3]?0.f:gv[3]);
            }
            #pragma unroll
            for (int r=0;r<4;r++){
                axs[se + r*16][sk] = b1(av[r]);
                if (anyneg) ans[se + r*16][sk] = b1(anv[r]);
            }
        }
        if (t < 64){
            #pragma unroll
            for (int j=0;j<4;j++){
                int m = (t+1)*16 + kq*4 + j;
                if (m < M_){
                    th[j] = theta_[m*N_ + n0+sn];
                    no[j] = noise[((size_t)(fv*M_ + m))*N_ + n0+sn];
                    fa[j] = fault[((size_t)(f*M_ + m))*N_ + n0+sn];
                } else { th[j]=0.f; no[j]=0.f; fa[j]=0.f; }
            }
            #pragma unroll
            for (int r=0;r<4;r++){
                int m = (t+1)*16 + sk;
                av[r] = (m < NIN_) ? a[(size_t)(fv*E_ + se + r*16)*NIN_ + m]
                                   : ((m == NIN_) ? 1.f : 0.f);
                if (anyneg) anv[r] = (m < M_) ? g_AN[(size_t)(fv*E_ + se + r*16)*M_ + m] : 0.f;
            }
        }
        __syncthreads();
        {
            uint32_t aw0 = *(const uint32_t*)&Wt[nw+g  ][2*t4];
            uint32_t aw1 = *(const uint32_t*)&Wt[nw+g+8][2*t4];
            uint32_t aw2 = *(const uint32_t*)&Wt[nw+g  ][2*t4+8];
            uint32_t aw3 = *(const uint32_t*)&Wt[nw+g+8][2*t4+8];
            uint32_t ag0 = *(const uint32_t*)&Gt[nw+g  ][2*t4];
            uint32_t ag1 = *(const uint32_t*)&Gt[nw+g+8][2*t4];
            uint32_t ag2 = *(const uint32_t*)&Gt[nw+g  ][2*t4+8];
            uint32_t ag3 = *(const uint32_t*)&Gt[nw+g+8][2*t4+8];
            #pragma unroll
            for (int c=0;c<4;c++){
                int e = ec0 + c*8 + g;
                uint32_t b0 = *(const uint32_t*)&axs[e][2*t4];
                uint32_t bb1 = *(const uint32_t*)&axs[e][2*t4+8];
                mma_bf16(zacc[c],  aw0, aw1, aw2, aw3, b0, bb1);
                mma_bf16(z2acc[c], ag0, ag1, ag2, ag3, b0, bb1);
            }
            if (anyneg){
                uint32_t q0 = *(const uint32_t*)&Wq[nw+g  ][2*t4];
                uint32_t q1 = *(const uint32_t*)&Wq[nw+g+8][2*t4];
                uint32_t q2 = *(const uint32_t*)&Wq[nw+g  ][2*t4+8];
                uint32_t q3 = *(const uint32_t*)&Wq[nw+g+8][2*t4+8];
                uint32_t h0 = *(const uint32_t*)&Gq[nw+g  ][2*t4];
                uint32_t h1 = *(const uint32_t*)&Gq[nw+g+8][2*t4];
                uint32_t h2 = *(const uint32_t*)&Gq[nw+g  ][2*t4+8];
                uint32_t h3 = *(const uint32_t*)&Gq[nw+g+8][2*t4+8];
                #pragma unroll
                for (int c=0;c<4;c++){
                    int e = ec0 + c*8 + g;
                    uint32_t b0 = *(const uint32_t*)&ans[e][2*t4];
                    uint32_t bb1 = *(const uint32_t*)&ans[e][2*t4+8];
                    mma_bf16(zacc[c],  q0, q1, q2, q3, b0, bb1);
                    mma_bf16(z2acc[c], h0, h1, h2, h3, b0, bb1);
                }
            }
        }
    }

    dsum_s[kq][sn] = dsum;
    __syncthreads();
    if (tid < 64)
        invd_s[tid] = 1.f/(dsum_s[0][tid]+dsum_s[1][tid]+dsum_s[2][tid]+dsum_s[3][tid] + 1e-10f);
    __syncthreads();

    const int r0 = nw + g, r1 = nw + g + 8;
    const float invd0 = invd_s[r0], invd1 = invd_s[r1];
    const float gs0 = g_sumabs[n0+r0] * (0.1f / gmin_of(n0+r0));
    const float gs1 = g_sumabs[n0+r1] * (0.1f / gmin_of(n0+r1));
    const int as0 = g_actsel[n0+r0], as1 = g_actsel[n0+r1];
    double cp = 0.0;
    #pragma unroll
    for (int c=0;c<4;c++){
        int e0 = ec0 + c*8 + 2*t4;
        float vals[4] = { zacc[c][0], zacc[c][1], zacc[c][2], zacc[c][3] };
        float v2[4]   = { z2acc[c][0], z2acc[c][1], z2acc[c][2], z2acc[c][3] };
        #pragma unroll
        for (int q=0;q<4;q++){
            int e  = e0 + (q & 1);
            int rr = (q < 2) ? r0 : r1;
            float invd = (q < 2) ? invd0 : invd1;
            float gsn  = (q < 2) ? gs0 : gs1;
            int   asel = (q < 2) ? as0 : as1;
            float zz = vals[q] * invd;
            float act = asel ? tanhf(zz) : (1.f/(1.f + expf(2.f - 4.f*zz)));
            out[(size_t)(fv*E_ + e)*N_ + n0 + rr] = act;
            cp += (double)zz * ((double)gsn*(double)zz - 2.0*(double)v2[q]);
        }
    }
    sred[tid] = cp;
    __syncthreads();
    for (int s=128; s>0; s>>=1){
        if (tid < s) sred[tid] += sred[tid+s];
        __syncthreads();
    }
    if (tid == 0) atomicAdd(&g_cross, sred[0]);
}

// ---------------- K6: neg powAB + finalize + reset state for next replay ----------------
__global__ void k6_fin(float* __restrict__ out)
{
    int tid = threadIdx.x;
    if (blockIdx.x == 0){
        __shared__ double sred[256];
        double s = 0.0;
        if (g_anyneg){
            for (int i = tid; i < F_*M_; i += 256)
                s += (double)g_gneg[i] * (double)g_BBf[i];
        }
        sred[tid] = s;
        __syncthreads();
        for (int st=128; st>0; st>>=1){
            if (tid < st) sred[tid] += sred[tid+st];
            __syncthreads();
        }
        if (tid == 0)
            out[(size_t)FV_*E_*N_] = (float)((g_powAB + g_cross + sred[0]) * (1.0/1024.0));
        __syncthreads();
        // reset what this block read
        for (int i = tid; i < F_*M_; i += 256){ g_gneg[i] = 0.f; g_BBf[i] = 0.f; }
        if (tid == 0){ g_powAB = 0.0; g_cross = 0.0; g_anyneg = 0; }
    } else {
        int base = (blockIdx.x - 1)*256 + tid;   // blocks 1..17 -> 0..4351
        if (base < N_){ g_gmax_not[base] = 0u; g_sumabs[base] = 0.f; }
        if (base < F_*M_) g_AAf[base] = 0.f;
        if (base < F_*NT2_) g_negflag[base] = 0;
    }
}

// ---------------- launch ----------------
extern "C" void kernel_launch(void* const* d_in, const int* in_sizes, int n_in,
                              void* d_out, int out_size)
{
    const float* a         = (const float*)d_in[0];
    const float* theta_    = (const float*)d_in[1];
    const float* coeff_act = (const float*)d_in[2];
    const float* coeff_neg = (const float*)d_in[3];
    const float* noise_u   = (const float*)d_in[4];
    const float* gum_act   = (const float*)d_in[5];
    const float* gum_neg   = (const float*)d_in[6];
    const float* fault     = (const float*)d_in[7];
    float* out = (float*)d_out;

    k1_theta<<<dim3(4,18),    256>>>(theta_, coeff_act, coeff_neg, gum_act, gum_neg);
    k3a_AA  <<<dim3(FV_,5,4), 256>>>(a);
    ksp     <<<dim3(F_,NT2_,9),256>>>(theta_, fault);
    k3b_an  <<<dim3(FV_,5,8), 256>>>(a);
    k5_slim <<<dim3(FV_,NT_), 256>>>(a, theta_, noise_u, fault, out);
    k5_full <<<dim3(FV_,NT_), 256>>>(a, theta_, noise_u, fault, out);
    k6_fin  <<<18, 256>>>(out);
}

// round 13
// speedup vs baseline: 1.0578x; 1.0578x over previous
#include <cuda_runtime.h>
#include <cuda_bf16.h>
#include <stdint.h>
#include <math.h>

#define F_ 4
#define V_ 4
#define E_ 64
#define NIN_ 1024
#define N_ 1024
#define M_ 1026
#define FV_ 16
#define NT_ 16     // k5 n-tiles of 64
#define NT2_ 8     // ksp n-tiles of 128

// ---------------- scratch (all zero-init; k6 restores zeros each call) ----------------
__device__ unsigned int g_gmax_not[N_];   // max(~bits(gi)) => gmin = ~max
__device__ float g_sumabs[N_];
__device__ int   g_actsel[N_];
__device__ int   g_bsel[M_];
__device__ float g_AN[FV_*E_*M_];
__device__ float g_AAf[F_*M_];
__device__ float g_BBf[F_*M_];
__device__ float g_gneg[F_*M_];
__device__ int   g_negflag[F_*NT2_];
__device__ int   g_anyneg;
__device__ double g_powAB;
__device__ double g_cross;

__device__ __forceinline__ float clampf(float x, float lo, float hi){
    return fminf(fmaxf(x, lo), hi);
}
__device__ __forceinline__ float gmin_of(int n){
    return __uint_as_float(~g_gmax_not[n]);
}
__device__ __forceinline__ uint16_t b1(float a){
    __nv_bfloat16 p = __float2bfloat16(a);
    return *reinterpret_cast<uint16_t*>(&p);
}
__device__ __forceinline__ uint32_t bpack(float a, float b){
    __nv_bfloat162 p = __floats2bfloat162_rn(a, b);
    return *reinterpret_cast<uint32_t*>(&p);
}
__device__ __forceinline__ void mma_bf16(float* d, uint32_t a0, uint32_t a1, uint32_t a2, uint32_t a3,
                                         uint32_t b0, uint32_t b1v){
    asm volatile("mma.sync.aligned.m16n8k16.row.col.f32.bf16.bf16.f32 "
        "{%0,%1,%2,%3}, {%4,%5,%6,%7}, {%8,%9}, {%0,%1,%2,%3};"
        : "+f"(d[0]), "+f"(d[1]), "+f"(d[2]), "+f"(d[3])
        : "r"(a0), "r"(a1), "r"(a2), "r"(a3), "r"(b0), "r"(b1v));
}
__device__ __forceinline__ uint32_t su32(const void* p){
    return (uint32_t)__cvta_generic_to_shared(p);
}
#define CPA16(dst, src) asm volatile("cp.async.cg.shared.global [%0], [%1], 16;" :: "r"(dst), "l"(src))
#define CPCOMMIT()      asm volatile("cp.async.commit_group;" ::: "memory")
#define CPWAIT1()       asm volatile("cp.async.wait_group 1;" ::: "memory")

// ---------------- K1: theta column min/sum + gumbel selections ----------------
__global__ void k1_theta(const float* __restrict__ theta_,
                         const float* __restrict__ coeff_act,
                         const float* __restrict__ coeff_neg,
                         const float* __restrict__ gum_act,
                         const float* __restrict__ gum_neg)
{
    int n  = blockIdx.x*256 + threadIdx.x;
    int m0 = blockIdx.y*57;
    float lmin = 3.4e38f, lsum = 0.f;
    #pragma unroll 3
    for (int r=0; r<57; r++){
        int m = m0 + r;
        float gi = fabsf(clampf(theta_[m*N_ + n], -1.f, 1.f));
        lmin = fminf(lmin, gi);
        lsum += gi;
    }
    atomicMax(&g_gmax_not[n], ~__float_as_uint(lmin));
    atomicAdd(&g_sumabs[n], lsum);

    if (blockIdx.y == 0){
        float v0 = clampf(coeff_act[n],    -1.f, 1.f) + gum_act[n];
        float v1 = clampf(coeff_act[N_+n], -1.f, 1.f) + gum_act[N_+n];
        g_actsel[n] = (v1 > v0) ? 1 : 0;
    } else if (blockIdx.y == 1){
        float v0 = clampf(coeff_neg[n],    -1.f, 1.f) + gum_neg[n];
        float v1 = clampf(coeff_neg[M_+n], -1.f, 1.f) + gum_neg[M_+n];
        g_bsel[n] = (v1 > v0) ? 1 : 0;
    } else if (blockIdx.y == 2){
        int m = 1024 + n;
        if (m < M_){
            float v0 = clampf(coeff_neg[m],    -1.f, 1.f) + gum_neg[m];
            float v1 = clampf(coeff_neg[M_+m], -1.f, 1.f) + gum_neg[M_+m];
            g_bsel[m] = (v1 > v0) ? 1 : 0;
        }
    }
}

// ---------------- K3a: AAf (320 blocks) ----------------
__global__ void k3a_AA(const float* __restrict__ a)
{
    int fv = blockIdx.x, f = fv >> 2;
    int m  = blockIdx.y*256 + threadIdx.x;
    int es = blockIdx.z;
    if (m >= M_) return;
    float AA = 0.f;
    #pragma unroll 4
    for (int r = 0; r < 16; r++){
        int e = es*16 + r;
        float ax = (m < NIN_) ? a[(size_t)(fv*E_+e)*NIN_ + m] : ((m == NIN_) ? 1.f : 0.f);
        AA += ax*ax;
    }
    atomicAdd(&g_AAf[f*M_ + m], AA);
}

// ---------------- KSP: neg flags + pos powAB + gneg ----------------
__global__ __launch_bounds__(256) void ksp(const float* __restrict__ theta_,
                                           const float* __restrict__ fault)
{
    int f  = blockIdx.x;
    int nt = blockIdx.y;
    int mc = blockIdx.z;
    int n  = nt*128 + (threadIdx.x & 127);
    int ms = threadIdx.x >> 7;
    float ginv = 0.1f / gmin_of(n);
    int neg = 0;
    double pab = 0.0;
    #pragma unroll 3
    for (int r=0; r<57; r++){
        int m = mc*114 + r*2 + ms;
        float tc = clampf(theta_[m*N_ + n], -1.f, 1.f);
        float gi = fabsf(tc);
        float th = (gi < 0.01f) ? 0.f : tc;
        float fa = fault[(f*M_ + m)*N_ + n];
        float g  = gi * ginv;
        float s  = th*fa;
        if (s < 0.f){ neg = 1; atomicAdd(&g_gneg[f*M_ + m], g); }
        else        { pab += (double)(g * g_AAf[f*M_ + m]); }
    }
    if (neg){ atomicOr(&g_negflag[f*NT2_ + nt], 1); atomicOr(&g_anyneg, 1); }
    __shared__ double sred[256];
    sred[threadIdx.x] = pab;
    __syncthreads();
    for (int s=128; s>0; s>>=1){
        if (threadIdx.x < s) sred[threadIdx.x] += sred[threadIdx.x+s];
        __syncthreads();
    }
    if (threadIdx.x == 0) atomicAdd(&g_powAB, sred[0]);
}

// ---------------- K3b: an/BBf (correctness path; 80 blocks so the dead path is cheap) --
__global__ void k3b_an(const float* __restrict__ a)
{
    if (g_anyneg == 0) return;
    int fv = blockIdx.x;
    int m  = blockIdx.y*256 + threadIdx.x;
    if (m >= M_) return;
    int bs = g_bsel[m];
    float BB = 0.f;
    for (int e=0; e<E_; e++){
        float ax = (m < NIN_) ? a[(size_t)(fv*E_+e)*NIN_ + m] : ((m == NIN_) ? 1.f : 0.f);
        float an;
        if (m == M_-1) an = 0.f;
        else           an = bs ? (1.f/(1.f + expf(4.f*ax - 2.f))) : (1.f - ax);
        g_AN[(size_t)(fv*E_+e)*M_ + m] = an;
        BB += an*an;
    }
    int f = fv >> 2;
    atomicAdd(&g_BBf[f*M_ + m], BB);
}

// ---------------- K5: bf16 mma.sync dual GEMM, cp.async depth-2 (R11-proven) ----------
__global__ __launch_bounds__(256, 2) void k5_mma(const float* __restrict__ a,
                                                 const float* __restrict__ theta_,
                                                 const float* __restrict__ noise,
                                                 const float* __restrict__ fault,
                                                 float* __restrict__ out)
{
    const int fv = blockIdx.x, f = fv >> 2;
    const int n0 = blockIdx.y * 64;
    const int tid = threadIdx.x;
    const int lane = tid & 31, w = tid >> 5;
    const bool anyneg = (g_negflag[f*NT2_ + (blockIdx.y >> 1)] != 0);

    __shared__ float rawTh[2][16][64], rawNo[2][16][64], rawFa[2][16][64];
    __shared__ uint16_t Wt[64][20], Gt[64][20], Wq[64][20], Gq[64][20];
    __shared__ uint16_t axs[64][20], ans[64][20];
    __shared__ float dsum_s[4][64];
    __shared__ float invd_s[64];
    __shared__ double sred[256];

    const int crow = tid >> 4;           // cp.async m-row within tile
    const int cch  = (tid & 15) * 4;     // float offset within 64-col row
    const int sn = tid & 63, kq = tid >> 6;   // W/G: col n0+sn, k = kq*4+j
    const int sk = tid & 15, se = tid >> 4;   // ax:  k = sk, e = se + 16r
    const int g = lane >> 2, t4 = lane & 3;
    const int nw = (w & 3) * 16, ec0 = (w >> 2) * 32;

    const float ginv = 0.1f / gmin_of(n0 + sn);
    float dsum = 0.f;
    float zacc[4][4], z2acc[4][4];
    #pragma unroll
    for (int c=0;c<4;c++)
        #pragma unroll
        for (int q=0;q<4;q++){ zacc[c][q]=0.f; z2acc[c][q]=0.f; }

    auto issue_tile = [&](int t, int s){
        int m = t*16 + crow;
        if (m < M_){
            CPA16(su32(&rawTh[s][crow][cch]), &theta_[(size_t)m*N_ + n0 + cch]);
            CPA16(su32(&rawNo[s][crow][cch]), &noise[((size_t)(fv*M_ + m))*N_ + n0 + cch]);
            CPA16(su32(&rawFa[s][crow][cch]), &fault[((size_t)(f*M_ + m))*N_ + n0 + cch]);
        }
    };

    issue_tile(0, 0); CPCOMMIT();
    issue_tile(1, 1); CPCOMMIT();

    float av[4], anv[4];
    #pragma unroll
    for (int r=0;r<4;r++){
        av[r]  = a[(size_t)(fv*E_ + se + r*16)*NIN_ + sk];
        anv[r] = anyneg ? g_AN[(size_t)(fv*E_ + se + r*16)*M_ + sk] : 0.f;
    }

    for (int t = 0; t < 65; t++){
        const int buf = t & 1;
        CPWAIT1();
        __syncthreads();
        // ---- stage W/G from raw smem (+ dsum) ----
        {
            float wv[4], gv[4]; bool pv[4];
            #pragma unroll
            for (int j=0;j<4;j++){
                int m = t*16 + kq*4 + j;
                bool vm = (m < M_);
                float thr = vm ? rawTh[buf][kq*4+j][sn] : 0.f;
                float nor = vm ? rawNo[buf][kq*4+j][sn] : 0.f;
                float far = vm ? rawFa[buf][kq*4+j][sn] : 0.f;
                float tc = clampf(thr, -1.f, 1.f);
                float gi = fabsf(tc);
                float thv = (gi < 0.01f) ? 0.f : tc;
                float gt = vm ? gi * ginv : 0.f;
                float tn = thv*(0.9f + 0.2f*nor)*far;
                wv[j] = fabsf(tn);
                gv[j] = gt;
                pv[j] = (tn >= 0.f);
                dsum += wv[j];
            }
            if (!anyneg){
                *(uint32_t*)&Wt[sn][kq*4]   = bpack(wv[0], wv[1]);
                *(uint32_t*)&Wt[sn][kq*4+2] = bpack(wv[2], wv[3]);
                *(uint32_t*)&Gt[sn][kq*4]   = bpack(gv[0], gv[1]);
                *(uint32_t*)&Gt[sn][kq*4+2] = bpack(gv[2], gv[3]);
            } else {
                *(uint32_t*)&Wt[sn][kq*4]   = bpack(pv[0]?wv[0]:0.f, pv[1]?wv[1]:0.f);
                *(uint32_t*)&Wt[sn][kq*4+2] = bpack(pv[2]?wv[2]:0.f, pv[3]?wv[3]:0.f);
                *(uint32_t*)&Wq[sn][kq*4]   = bpack(pv[0]?0.f:wv[0], pv[1]?0.f:wv[1]);
                *(uint32_t*)&Wq[sn][kq*4+2] = bpack(pv[2]?0.f:wv[2], pv[3]?0.f:wv[3]);
                *(uint32_t*)&Gt[sn][kq*4]   = bpack(pv[0]?gv[0]:0.f, pv[1]?gv[1]:0.f);
                *(uint32_t*)&Gt[sn][kq*4+2] = bpack(pv[2]?gv[2]:0.f, pv[3]?gv[3]:0.f);
                *(uint32_t*)&Gq[sn][kq*4]   = bpack(pv[0]?0.f:gv[0], pv[1]?0.f:gv[1]);
                *(uint32_t*)&Gq[sn][kq*4+2] = bpack(pv[2]?0.f:gv[2], pv[3]?0.f:gv[3]);
            }
            #pragma unroll
            for (int r=0;r<4;r++){
                axs[se + r*16][sk] = b1(av[r]);
                if (anyneg) ans[se + r*16][sk] = b1(anv[r]);
            }
        }
        // ---- prefetch a regs for t+1 ----
        if (t < 64){
            #pragma unroll
            for (int r=0;r<4;r++){
                int m = (t+1)*16 + sk;
                av[r] = (m < NIN_) ? a[(size_t)(fv*E_ + se + r*16)*NIN_ + m]
                                   : ((m == NIN_) ? 1.f : 0.f);
                if (anyneg) anv[r] = (m < M_) ? g_AN[(size_t)(fv*E_ + se + r*16)*M_ + m] : 0.f;
            }
        }
        __syncthreads();
        // ---- issue raw tile t+2 ----
        if (t + 2 < 65) issue_tile(t + 2, buf);
        CPCOMMIT();
        // ---- mma ----
        {
            uint32_t aw0 = *(const uint32_t*)&Wt[nw+g  ][2*t4];
            uint32_t aw1 = *(const uint32_t*)&Wt[nw+g+8][2*t4];
            uint32_t aw2 = *(const uint32_t*)&Wt[nw+g  ][2*t4+8];
            uint32_t aw3 = *(const uint32_t*)&Wt[nw+g+8][2*t4+8];
            uint32_t ag0 = *(const uint32_t*)&Gt[nw+g  ][2*t4];
            uint32_t ag1 = *(const uint32_t*)&Gt[nw+g+8][2*t4];
            uint32_t ag2 = *(const uint32_t*)&Gt[nw+g  ][2*t4+8];
            uint32_t ag3 = *(const uint32_t*)&Gt[nw+g+8][2*t4+8];
            #pragma unroll
            for (int c=0;c<4;c++){
                int e = ec0 + c*8 + g;
                uint32_t b0  = *(const uint32_t*)&axs[e][2*t4];
                uint32_t bb1 = *(const uint32_t*)&axs[e][2*t4+8];
                mma_bf16(zacc[c],  aw0, aw1, aw2, aw3, b0, bb1);
                mma_bf16(z2acc[c], ag0, ag1, ag2, ag3, b0, bb1);
            }
            if (anyneg){
                uint32_t q0 = *(const uint32_t*)&Wq[nw+g  ][2*t4];
                uint32_t q1 = *(const uint32_t*)&Wq[nw+g+8][2*t4];
                uint32_t q2 = *(const uint32_t*)&Wq[nw+g  ][2*t4+8];
                uint32_t q3 = *(const uint32_t*)&Wq[nw+g+8][2*t4+8];
                uint32_t h0 = *(const uint32_t*)&Gq[nw+g  ][2*t4];
                uint32_t h1 = *(const uint32_t*)&Gq[nw+g+8][2*t4];
                uint32_t h2 = *(const uint32_t*)&Gq[nw+g  ][2*t4+8];
                uint32_t h3 = *(const uint32_t*)&Gq[nw+g+8][2*t4+8];
                #pragma unroll
                for (int c=0;c<4;c++){
                    int e = ec0 + c*8 + g;
                    uint32_t b0  = *(const uint32_t*)&ans[e][2*t4];
                    uint32_t bb1 = *(const uint32_t*)&ans[e][2*t4+8];
                    mma_bf16(zacc[c],  q0, q1, q2, q3, b0, bb1);
                    mma_bf16(z2acc[c], h0, h1, h2, h3, b0, bb1);
                }
            }
        }
    }

    // ---- D reduction ----
    dsum_s[kq][sn] = dsum;
    __syncthreads();
    if (tid < 64)
        invd_s[tid] = 1.f/(dsum_s[0][tid]+dsum_s[1][tid]+dsum_s[2][tid]+dsum_s[3][tid] + 1e-10f);
    __syncthreads();

    // ---- epilogue ----
    const int r0 = nw + g, r1 = nw + g + 8;
    const float invd0 = invd_s[r0], invd1 = invd_s[r1];
    const float gs0 = g_sumabs[n0+r0] * (0.1f / gmin_of(n0+r0));
    const float gs1 = g_sumabs[n0+r1] * (0.1f / gmin_of(n0+r1));
    const int as0 = g_actsel[n0+r0], as1 = g_actsel[n0+r1];
    double cp = 0.0;
    #pragma unroll
    for (int c=0;c<4;c++){
        int e0 = ec0 + c*8 + 2*t4;
        float vals[4] = { zacc[c][0], zacc[c][1], zacc[c][2], zacc[c][3] };
        float v2[4]   = { z2acc[c][0], z2acc[c][1], z2acc[c][2], z2acc[c][3] };
        #pragma unroll
        for (int q=0;q<4;q++){
            int e  = e0 + (q & 1);
            int rr = (q < 2) ? r0 : r1;
            float invd = (q < 2) ? invd0 : invd1;
            float gsn  = (q < 2) ? gs0 : gs1;
            int   asel = (q < 2) ? as0 : as1;
            float zz = vals[q] * invd;
            float act = asel ? tanhf(zz) : (1.f/(1.f + expf(2.f - 4.f*zz)));
            out[(size_t)(fv*E_ + e)*N_ + n0 + rr] = act;
            cp += (double)zz * ((double)gsn*(double)zz - 2.0*(double)v2[q]);
        }
    }
    sred[tid] = cp;
    __syncthreads();
    for (int s=128; s>0; s>>=1){
        if (tid < s) sred[tid] += sred[tid+s];
        __syncthreads();
    }
    if (tid == 0) atomicAdd(&g_cross, sred[0]);
}

// ---------------- K6: neg powAB + finalize + reset state for next call ----------------
__global__ void k6_fin(float* __restrict__ out)
{
    int tid = threadIdx.x;
    if (blockIdx.x == 0){
        __shared__ double sred[256];
        double s = 0.0;
        if (g_anyneg){
            for (int i = tid; i < F_*M_; i += 256)
                s += (double)g_gneg[i] * (double)g_BBf[i];
        }
        sred[tid] = s;
        __syncthreads();
        for (int st=128; st>0; st>>=1){
            if (tid < st) sred[tid] += sred[tid+st];
            __syncthreads();
        }
        if (tid == 0)
            out[(size_t)FV_*E_*N_] = (float)((g_powAB + g_cross + sred[0]) * (1.0/1024.0));
        __syncthreads();
        for (int i = tid; i < F_*M_; i += 256){ g_gneg[i] = 0.f; g_BBf[i] = 0.f; }
        if (tid == 0){ g_powAB = 0.0; g_cross = 0.0; g_anyneg = 0; }
    } else {
        int base = (blockIdx.x - 1)*256 + tid;   // blocks 1..17 -> 0..4351
        if (base < N_){ g_gmax_not[base] = 0u; g_sumabs[base] = 0.f; }
        if (base < F_*M_) g_AAf[base] = 0.f;
        if (base < F_*NT2_) g_negflag[base] = 0;
    }
}

// ---------------- launch ----------------
extern "C" void kernel_launch(void* const* d_in, const int* in_sizes, int n_in,
                              void* d_out, int out_size)
{
    const float* a         = (const float*)d_in[0];
    const float* theta_    = (const float*)d_in[1];
    const float* coeff_act = (const float*)d_in[2];
    const float* coeff_neg = (const float*)d_in[3];
    const float* noise_u   = (const float*)d_in[4];
    const float* gum_act   = (const float*)d_in[5];
    const float* gum_neg   = (const float*)d_in[6];
    const float* fault     = (const float*)d_in[7];
    float* out = (float*)d_out;

    k1_theta<<<dim3(4,18),    256>>>(theta_, coeff_act, coeff_neg, gum_act, gum_neg);
    k3a_AA  <<<dim3(FV_,5,4), 256>>>(a);
    ksp     <<<dim3(F_,NT2_,9),256>>>(theta_, fault);
    k3b_an  <<<dim3(FV_,5),   256>>>(a);
    k5_mma  <<<dim3(FV_,NT_), 256>>>(a, theta_, noise_u, fault, out);
    k6_fin  <<<18, 256>>>(out);
}

// round 14
// speedup vs baseline: 1.0816x; 1.0226x over previous
#include <cuda_runtime.h>
#include <cuda_bf16.h>
#include <stdint.h>
#include <math.h>

#define F_ 4
#define V_ 4
#define E_ 64
#define NIN_ 1024
#define N_ 1024
#define M_ 1026
#define FV_ 16
#define NT_ 16     // k5 n-tiles of 64
#define NT2_ 8     // ksp n-tiles of 128

// ---------------- scratch (all zero-init; k6 restores zeros each call) ----------------
__device__ unsigned int g_gmax_not[N_];   // max(~bits(gi)) => gmin = ~max
__device__ float g_sumabs[N_];
__device__ int   g_actsel[N_];
__device__ int   g_bsel[M_];
__device__ float g_AAf[F_*M_];
__device__ float g_BBf[F_*M_];
__device__ float g_gneg[F_*M_];
__device__ int   g_negflag[F_*NT2_];
__device__ int   g_anyneg;
__device__ double g_powAB;
__device__ double g_cross;

__device__ __forceinline__ float clampf(float x, float lo, float hi){
    return fminf(fmaxf(x, lo), hi);
}
__device__ __forceinline__ float gmin_of(int n){
    return __uint_as_float(~g_gmax_not[n]);
}
__device__ __forceinline__ uint16_t b1(float a){
    __nv_bfloat16 p = __float2bfloat16(a);
    return *reinterpret_cast<uint16_t*>(&p);
}
__device__ __forceinline__ uint32_t bpack(float a, float b){
    __nv_bfloat162 p = __floats2bfloat162_rn(a, b);
    return *reinterpret_cast<uint32_t*>(&p);
}
__device__ __forceinline__ void mma_bf16(float* d, uint32_t a0, uint32_t a1, uint32_t a2, uint32_t a3,
                                         uint32_t b0, uint32_t b1v){
    asm volatile("mma.sync.aligned.m16n8k16.row.col.f32.bf16.bf16.f32 "
        "{%0,%1,%2,%3}, {%4,%5,%6,%7}, {%8,%9}, {%0,%1,%2,%3};"
        : "+f"(d[0]), "+f"(d[1]), "+f"(d[2]), "+f"(d[3])
        : "r"(a0), "r"(a1), "r"(a2), "r"(a3), "r"(b0), "r"(b1v));
}
__device__ __forceinline__ uint32_t su32(const void* p){
    return (uint32_t)__cvta_generic_to_shared(p);
}
#define CPA16(dst, src) asm volatile("cp.async.cg.shared.global [%0], [%1], 16;" :: "r"(dst), "l"(src))
#define CPCOMMIT()      asm volatile("cp.async.commit_group;" ::: "memory")
#define CPWAIT1()       asm volatile("cp.async.wait_group 1;" ::: "memory")

__device__ __forceinline__ float an_of(float ax, int bs, int m){
    if (m == M_-1) return 0.f;
    return bs ? (1.f/(1.f + expf(4.f*ax - 2.f))) : (1.f - ax);
}

// ---------------- KPREP: theta stats + gumbel sel (blocks 0..71) | AAf/BBf (72..391) ----
__global__ void kprep(const float* __restrict__ theta_,
                      const float* __restrict__ coeff_act,
                      const float* __restrict__ coeff_neg,
                      const float* __restrict__ gum_act,
                      const float* __restrict__ gum_neg,
                      const float* __restrict__ a)
{
    int b = blockIdx.x;
    int tid = threadIdx.x;
    if (b < 72){
        int bx = b & 3, by = b >> 2;     // 4 x 18
        int n  = bx*256 + tid;
        int m0 = by*57;
        float lmin = 3.4e38f, lsum = 0.f;
        #pragma unroll 3
        for (int r=0; r<57; r++){
            int m = m0 + r;
            float gi = fabsf(clampf(theta_[m*N_ + n], -1.f, 1.f));
            lmin = fminf(lmin, gi);
            lsum += gi;
        }
        atomicMax(&g_gmax_not[n], ~__float_as_uint(lmin));
        atomicAdd(&g_sumabs[n], lsum);

        if (by == 0){
            float v0 = clampf(coeff_act[n],    -1.f, 1.f) + gum_act[n];
            float v1 = clampf(coeff_act[N_+n], -1.f, 1.f) + gum_act[N_+n];
            g_actsel[n] = (v1 > v0) ? 1 : 0;
        } else if (by == 1){
            float v0 = clampf(coeff_neg[n],    -1.f, 1.f) + gum_neg[n];
            float v1 = clampf(coeff_neg[M_+n], -1.f, 1.f) + gum_neg[M_+n];
            g_bsel[n] = (v1 > v0) ? 1 : 0;
        } else if (by == 2){
            int m = 1024 + n;
            if (m < M_){
                float v0 = clampf(coeff_neg[m],    -1.f, 1.f) + gum_neg[m];
                float v1 = clampf(coeff_neg[M_+m], -1.f, 1.f) + gum_neg[M_+m];
                g_bsel[m] = (v1 > v0) ? 1 : 0;
            }
        }
    } else {
        int bb = b - 72;                 // 320 = 16 fv x (5 m-chunks x 4 e-slices)
        int fv = bb & 15, rem = bb >> 4;
        int my = rem % 5, es = rem / 5;
        int m  = my*256 + tid;
        if (m >= M_) return;
        // bs computed from inputs (no dependency on k1-half)
        float v0 = clampf(coeff_neg[m],    -1.f, 1.f) + gum_neg[m];
        float v1 = clampf(coeff_neg[M_+m], -1.f, 1.f) + gum_neg[M_+m];
        int bs = (v1 > v0) ? 1 : 0;
        float AA = 0.f, BB = 0.f;
        #pragma unroll 4
        for (int r = 0; r < 16; r++){
            int e = es*16 + r;
            float ax = (m < NIN_) ? a[(size_t)(fv*E_+e)*NIN_ + m] : ((m == NIN_) ? 1.f : 0.f);
            float an = an_of(ax, bs, m);
            AA += ax*ax;
            BB += an*an;
        }
        int f = fv >> 2;
        atomicAdd(&g_AAf[f*M_ + m], AA);
        atomicAdd(&g_BBf[f*M_ + m], BB);
    }
}

// ---------------- KSP: neg flags + pos powAB + gneg ----------------
__global__ __launch_bounds__(256) void ksp(const float* __restrict__ theta_,
                                           const float* __restrict__ fault)
{
    int f  = blockIdx.x;
    int nt = blockIdx.y;
    int mc = blockIdx.z;
    int n  = nt*128 + (threadIdx.x & 127);
    int ms = threadIdx.x >> 7;
    float ginv = 0.1f / gmin_of(n);
    int neg = 0;
    double pab = 0.0;
    #pragma unroll 3
    for (int r=0; r<57; r++){
        int m = mc*114 + r*2 + ms;
        float tc = clampf(theta_[m*N_ + n], -1.f, 1.f);
        float gi = fabsf(tc);
        float th = (gi < 0.01f) ? 0.f : tc;
        float fa = fault[(f*M_ + m)*N_ + n];
        float g  = gi * ginv;
        float s  = th*fa;
        if (s < 0.f){ neg = 1; atomicAdd(&g_gneg[f*M_ + m], g); }
        else        { pab += (double)(g * g_AAf[f*M_ + m]); }
    }
    if (neg){ atomicOr(&g_negflag[f*NT2_ + nt], 1); atomicOr(&g_anyneg, 1); }
    __shared__ double sred[256];
    sred[threadIdx.x] = pab;
    __syncthreads();
    for (int s=128; s>0; s>>=1){
        if (threadIdx.x < s) sred[threadIdx.x] += sred[threadIdx.x+s];
        __syncthreads();
    }
    if (threadIdx.x == 0) atomicAdd(&g_powAB, sred[0]);
}

// ---------------- K5: bf16 mma.sync dual GEMM, cp.async depth-2 (hot path unchanged) ----
__global__ __launch_bounds__(256, 2) void k5_mma(const float* __restrict__ a,
                                                 const float* __restrict__ theta_,
                                                 const float* __restrict__ noise,
                                                 const float* __restrict__ fault,
                                                 float* __restrict__ out)
{
    const int fv = blockIdx.x, f = fv >> 2;
    const int n0 = blockIdx.y * 64;
    const int tid = threadIdx.x;
    const int lane = tid & 31, w = tid >> 5;
    const bool anyneg = (g_negflag[f*NT2_ + (blockIdx.y >> 1)] != 0);

    __shared__ float rawTh[2][16][64], rawNo[2][16][64], rawFa[2][16][64];
    __shared__ uint16_t Wt[64][20], Gt[64][20], Wq[64][20], Gq[64][20];
    __shared__ uint16_t axs[64][20], ans[64][20];
    __shared__ float dsum_s[4][64];
    __shared__ float invd_s[64];
    __shared__ double sred[256];

    const int crow = tid >> 4;           // cp.async m-row within tile
    const int cch  = (tid & 15) * 4;     // float offset within 64-col row
    const int sn = tid & 63, kq = tid >> 6;   // W/G: col n0+sn, k = kq*4+j
    const int sk = tid & 15, se = tid >> 4;   // ax:  k = sk, e = se + 16r
    const int g = lane >> 2, t4 = lane & 3;
    const int nw = (w & 3) * 16, ec0 = (w >> 2) * 32;

    const float ginv = 0.1f / gmin_of(n0 + sn);
    float dsum = 0.f;
    float zacc[4][4], z2acc[4][4];
    #pragma unroll
    for (int c=0;c<4;c++)
        #pragma unroll
        for (int q=0;q<4;q++){ zacc[c][q]=0.f; z2acc[c][q]=0.f; }

    auto issue_tile = [&](int t, int s){
        int m = t*16 + crow;
        if (m < M_){
            CPA16(su32(&rawTh[s][crow][cch]), &theta_[(size_t)m*N_ + n0 + cch]);
            CPA16(su32(&rawNo[s][crow][cch]), &noise[((size_t)(fv*M_ + m))*N_ + n0 + cch]);
            CPA16(su32(&rawFa[s][crow][cch]), &fault[((size_t)(f*M_ + m))*N_ + n0 + cch]);
        }
    };

    issue_tile(0, 0); CPCOMMIT();
    issue_tile(1, 1); CPCOMMIT();

    float av[4], anv[4];
    {
        int m = sk;
        int bs = anyneg ? g_bsel[m] : 0;
        #pragma unroll
        for (int r=0;r<4;r++){
            av[r]  = a[(size_t)(fv*E_ + se + r*16)*NIN_ + m];
            anv[r] = anyneg ? an_of(av[r], bs, m) : 0.f;
        }
    }

    for (int t = 0; t < 65; t++){
        const int buf = t & 1;
        CPWAIT1();
        __syncthreads();
        // ---- stage W/G from raw smem (+ dsum) ----
        {
            float wv[4], gv[4]; bool pv[4];
            #pragma unroll
            for (int j=0;j<4;j++){
                int m = t*16 + kq*4 + j;
                bool vm = (m < M_);
                float thr = vm ? rawTh[buf][kq*4+j][sn] : 0.f;
                float nor = vm ? rawNo[buf][kq*4+j][sn] : 0.f;
                float far = vm ? rawFa[buf][kq*4+j][sn] : 0.f;
                float tc = clampf(thr, -1.f, 1.f);
                float gi = fabsf(tc);
                float thv = (gi < 0.01f) ? 0.f : tc;
                float gt = vm ? gi * ginv : 0.f;
                float tn = thv*(0.9f + 0.2f*nor)*far;
                wv[j] = fabsf(tn);
                gv[j] = gt;
                pv[j] = (tn >= 0.f);
                dsum += wv[j];
            }
            if (!anyneg){
                *(uint32_t*)&Wt[sn][kq*4]   = bpack(wv[0], wv[1]);
                *(uint32_t*)&Wt[sn][kq*4+2] = bpack(wv[2], wv[3]);
                *(uint32_t*)&Gt[sn][kq*4]   = bpack(gv[0], gv[1]);
                *(uint32_t*)&Gt[sn][kq*4+2] = bpack(gv[2], gv[3]);
            } else {
                *(uint32_t*)&Wt[sn][kq*4]   = bpack(pv[0]?wv[0]:0.f, pv[1]?wv[1]:0.f);
                *(uint32_t*)&Wt[sn][kq*4+2] = bpack(pv[2]?wv[2]:0.f, pv[3]?wv[3]:0.f);
                *(uint32_t*)&Wq[sn][kq*4]   = bpack(pv[0]?0.f:wv[0], pv[1]?0.f:wv[1]);
                *(uint32_t*)&Wq[sn][kq*4+2] = bpack(pv[2]?0.f:wv[2], pv[3]?0.f:wv[3]);
                *(uint32_t*)&Gt[sn][kq*4]   = bpack(pv[0]?gv[0]:0.f, pv[1]?gv[1]:0.f);
                *(uint32_t*)&Gt[sn][kq*4+2] = bpack(pv[2]?gv[2]:0.f, pv[3]?gv[3]:0.f);
                *(uint32_t*)&Gq[sn][kq*4]   = bpack(pv[0]?0.f:gv[0], pv[1]?0.f:gv[1]);
                *(uint32_t*)&Gq[sn][kq*4+2] = bpack(pv[2]?0.f:gv[2], pv[3]?0.f:gv[3]);
            }
            #pragma unroll
            for (int r=0;r<4;r++){
                axs[se + r*16][sk] = b1(av[r]);
                if (anyneg) ans[se + r*16][sk] = b1(anv[r]);
            }
        }
        // ---- prefetch a regs for t+1 ----
        if (t < 64){
            int m = (t+1)*16 + sk;
            int bs = (anyneg && m < M_) ? g_bsel[m] : 0;
            #pragma unroll
            for (int r=0;r<4;r++){
                av[r] = (m < NIN_) ? a[(size_t)(fv*E_ + se + r*16)*NIN_ + m]
                                   : ((m == NIN_) ? 1.f : 0.f);
                if (anyneg) anv[r] = (m < M_) ? an_of(av[r], bs, m) : 0.f;
            }
        }
        __syncthreads();
        // ---- issue raw tile t+2 ----
        if (t + 2 < 65) issue_tile(t + 2, buf);
        CPCOMMIT();
        // ---- mma ----
        {
            uint32_t aw0 = *(const uint32_t*)&Wt[nw+g  ][2*t4];
            uint32_t aw1 = *(const uint32_t*)&Wt[nw+g+8][2*t4];
            uint32_t aw2 = *(const uint32_t*)&Wt[nw+g  ][2*t4+8];
            uint32_t aw3 = *(const uint32_t*)&Wt[nw+g+8][2*t4+8];
            uint32_t ag0 = *(const uint32_t*)&Gt[nw+g  ][2*t4];
            uint32_t ag1 = *(const uint32_t*)&Gt[nw+g+8][2*t4];
            uint32_t ag2 = *(const uint32_t*)&Gt[nw+g  ][2*t4+8];
            uint32_t ag3 = *(const uint32_t*)&Gt[nw+g+8][2*t4+8];
            #pragma unroll
            for (int c=0;c<4;c++){
                int e = ec0 + c*8 + g;
                uint32_t b0  = *(const uint32_t*)&axs[e][2*t4];
                uint32_t bb1 = *(const uint32_t*)&axs[e][2*t4+8];
                mma_bf16(zacc[c],  aw0, aw1, aw2, aw3, b0, bb1);
                mma_bf16(z2acc[c], ag0, ag1, ag2, ag3, b0, bb1);
            }
            if (anyneg){
                uint32_t q0 = *(const uint32_t*)&Wq[nw+g  ][2*t4];
                uint32_t q1 = *(const uint32_t*)&Wq[nw+g+8][2*t4];
                uint32_t q2 = *(const uint32_t*)&Wq[nw+g  ][2*t4+8];
                uint32_t q3 = *(const uint32_t*)&Wq[nw+g+8][2*t4+8];
                uint32_t h0 = *(const uint32_t*)&Gq[nw+g  ][2*t4];
                uint32_t h1 = *(const uint32_t*)&Gq[nw+g+8][2*t4];
                uint32_t h2 = *(const uint32_t*)&Gq[nw+g  ][2*t4+8];
                uint32_t h3 = *(const uint32_t*)&Gq[nw+g+8][2*t4+8];
                #pragma unroll
                for (int c=0;c<4;c++){
                    int e = ec0 + c*8 + g;
                    uint32_t b0  = *(const uint32_t*)&ans[e][2*t4];
                    uint32_t bb1 = *(const uint32_t*)&ans[e][2*t4+8];
                    mma_bf16(zacc[c],  q0, q1, q2, q3, b0, bb1);
                    mma_bf16(z2acc[c], h0, h1, h2, h3, b0, bb1);
                }
            }
        }
    }

    // ---- D reduction ----
    dsum_s[kq][sn] = dsum;
    __syncthreads();
    if (tid < 64)
        invd_s[tid] = 1.f/(dsum_s[0][tid]+dsum_s[1][tid]+dsum_s[2][tid]+dsum_s[3][tid] + 1e-10f);
    __syncthreads();

    // ---- epilogue ----
    const int r0 = nw + g, r1 = nw + g + 8;
    const float invd0 = invd_s[r0], invd1 = invd_s[r1];
    const float gs0 = g_sumabs[n0+r0] * (0.1f / gmin_of(n0+r0));
    const float gs1 = g_sumabs[n0+r1] * (0.1f / gmin_of(n0+r1));
    const int as0 = g_actsel[n0+r0], as1 = g_actsel[n0+r1];
    double cp = 0.0;
    #pragma unroll
    for (int c=0;c<4;c++){
        int e0 = ec0 + c*8 + 2*t4;
        float vals[4] = { zacc[c][0], zacc[c][1], zacc[c][2], zacc[c][3] };
        float v2[4]   = { z2acc[c][0], z2acc[c][1], z2acc[c][2], z2acc[c][3] };
        #pragma unroll
        for (int q=0;q<4;q++){
            int e  = e0 + (q & 1);
            int rr = (q < 2) ? r0 : r1;
            float invd = (q < 2) ? invd0 : invd1;
            float gsn  = (q < 2) ? gs0 : gs1;
            int   asel = (q < 2) ? as0 : as1;
            float zz = vals[q] * invd;
            float act = asel ? tanhf(zz) : (1.f/(1.f + expf(2.f - 4.f*zz)));
            out[(size_t)(fv*E_ + e)*N_ + n0 + rr] = act;
            cp += (double)zz * ((double)gsn*(double)zz - 2.0*(double)v2[q]);
        }
    }
    sred[tid] = cp;
    __syncthreads();
    for (int s=128; s>0; s>>=1){
        if (tid < s) sred[tid] += sred[tid+s];
        __syncthreads();
    }
    if (tid == 0) atomicAdd(&g_cross, sred[0]);
}

// ---------------- K6: neg powAB + finalize + reset state for next call ----------------
__global__ void k6_fin(float* __restrict__ out)
{
    int tid = threadIdx.x;
    if (blockIdx.x == 0){
        __shared__ double sred[256];
        double s = 0.0;
        if (g_anyneg){
            for (int i = tid; i < F_*M_; i += 256)
                s += (double)g_gneg[i] * (double)g_BBf[i];
        }
        sred[tid] = s;
        __syncthreads();
        for (int st=128; st>0; st>>=1){
            if (tid < st) sred[tid] += sred[tid+st];
            __syncthreads();
        }
        if (tid == 0)
            out[(size_t)FV_*E_*N_] = (float)((g_powAB + g_cross + sred[0]) * (1.0/1024.0));
        __syncthreads();
        for (int i = tid; i < F_*M_; i += 256){ g_gneg[i] = 0.f; g_BBf[i] = 0.f; }
        if (tid == 0){ g_powAB = 0.0; g_cross = 0.0; g_anyneg = 0; }
    } else {
        int base = (blockIdx.x - 1)*256 + tid;   // blocks 1..17 -> 0..4351
        if (base < N_){ g_gmax_not[base] = 0u; g_sumabs[base] = 0.f; }
        if (base < F_*M_) g_AAf[base] = 0.f;
        if (base < F_*NT2_) g_negflag[base] = 0;
    }
}

// ---------------- launch ----------------
extern "C" void kernel_launch(void* const* d_in, const int* in_sizes, int n_in,
                              void* d_out, int out_size)
{
    const float* a         = (const float*)d_in[0];
    const float* theta_    = (const float*)d_in[1];
    const float* coeff_act = (const float*)d_in[2];
    const float* coeff_neg = (const float*)d_in[3];
    const float* noise_u   = (const float*)d_in[4];
    const float* gum_act   = (const float*)d_in[5];
    const float* gum_neg   = (const float*)d_in[6];
    const float* fault     = (const float*)d_in[7];
    float* out = (float*)d_out;

    kprep <<<392, 256>>>(theta_, coeff_act, coeff_neg, gum_act, gum_neg, a);
    ksp   <<<dim3(F_,NT2_,9),256>>>(theta_, fault);
    k5_mma<<<dim3(FV_,NT_), 256>>>(a, theta_, noise_u, fault, out);
    k6_fin<<<18, 256>>>(out);
}

// round 15
// speedup vs baseline: 1.0920x; 1.0095x over previous
#include <cuda_runtime.h>
#include <cuda_bf16.h>
#include <stdint.h>
#include <math.h>

#define F_ 4
#define V_ 4
#define E_ 64
#define NIN_ 1024
#define N_ 1024
#define M_ 1026
#define FV_ 16
#define NT_ 16     // k5 n-tiles of 64
#define NT2_ 8     // ksp n-tiles of 128

// ---------------- scratch (all zero-init; k6 restores zeros each call) ----------------
__device__ unsigned int g_gmax_not[N_];   // max(~bits(gi)) => gmin = ~max
__device__ float g_sumabs[N_];
__device__ int   g_actsel[N_];
__device__ int   g_bsel[M_];
__device__ float g_AAf[F_*M_];
__device__ float g_BBf[F_*M_];
__device__ float g_gneg[F_*M_];
__device__ int   g_negflag[F_*NT2_];
__device__ int   g_anyneg;
__device__ double g_powAB;
__device__ double g_cross;

__device__ __forceinline__ float clampf(float x, float lo, float hi){
    return fminf(fmaxf(x, lo), hi);
}
__device__ __forceinline__ float gmin_of(int n){
    return __uint_as_float(~g_gmax_not[n]);
}
__device__ __forceinline__ uint16_t b1(float a){
    __nv_bfloat16 p = __float2bfloat16(a);
    return *reinterpret_cast<uint16_t*>(&p);
}
__device__ __forceinline__ uint32_t bpack(float a, float b){
    __nv_bfloat162 p = __floats2bfloat162_rn(a, b);
    return *reinterpret_cast<uint32_t*>(&p);
}
__device__ __forceinline__ void mma_bf16(float* d, uint32_t a0, uint32_t a1, uint32_t a2, uint32_t a3,
                                         uint32_t b0, uint32_t b1v){
    asm volatile("mma.sync.aligned.m16n8k16.row.col.f32.bf16.bf16.f32 "
        "{%0,%1,%2,%3}, {%4,%5,%6,%7}, {%8,%9}, {%0,%1,%2,%3};"
        : "+f"(d[0]), "+f"(d[1]), "+f"(d[2]), "+f"(d[3])
        : "r"(a0), "r"(a1), "r"(a2), "r"(a3), "r"(b0), "r"(b1v));
}
__device__ __forceinline__ uint32_t su32(const void* p){
    return (uint32_t)__cvta_generic_to_shared(p);
}
#define CPA16(dst, src) asm volatile("cp.async.cg.shared.global [%0], [%1], 16;" :: "r"(dst), "l"(src))
#define CPCOMMIT()      asm volatile("cp.async.commit_group;" ::: "memory")
#define CPWAIT1()       asm volatile("cp.async.wait_group 1;" ::: "memory")

__device__ __forceinline__ float an_of(float ax, int bs, int m){
    if (m == M_-1) return 0.f;
    return bs ? (1.f/(1.f + expf(4.f*ax - 2.f))) : (1.f - ax);
}

// ---------------- KPREP: theta stats + gumbel sel (blocks 0..71) | AAf/BBf (72..391) ----
__global__ void kprep(const float* __restrict__ theta_,
                      const float* __restrict__ coeff_act,
                      const float* __restrict__ coeff_neg,
                      const float* __restrict__ gum_act,
                      const float* __restrict__ gum_neg,
                      const float* __restrict__ a)
{
    int b = blockIdx.x;
    int tid = threadIdx.x;
    if (b < 72){
        int bx = b & 3, by = b >> 2;     // 4 x 18
        int n  = bx*256 + tid;
        int m0 = by*57;
        float lmin = 3.4e38f, lsum = 0.f;
        #pragma unroll 3
        for (int r=0; r<57; r++){
            int m = m0 + r;
            float gi = fabsf(clampf(theta_[m*N_ + n], -1.f, 1.f));
            lmin = fminf(lmin, gi);
            lsum += gi;
        }
        atomicMax(&g_gmax_not[n], ~__float_as_uint(lmin));
        atomicAdd(&g_sumabs[n], lsum);

        if (by == 0){
            float v0 = clampf(coeff_act[n],    -1.f, 1.f) + gum_act[n];
            float v1 = clampf(coeff_act[N_+n], -1.f, 1.f) + gum_act[N_+n];
            g_actsel[n] = (v1 > v0) ? 1 : 0;
        } else if (by == 1){
            float v0 = clampf(coeff_neg[n],    -1.f, 1.f) + gum_neg[n];
            float v1 = clampf(coeff_neg[M_+n], -1.f, 1.f) + gum_neg[M_+n];
            g_bsel[n] = (v1 > v0) ? 1 : 0;
        } else if (by == 2){
            int m = 1024 + n;
            if (m < M_){
                float v0 = clampf(coeff_neg[m],    -1.f, 1.f) + gum_neg[m];
                float v1 = clampf(coeff_neg[M_+m], -1.f, 1.f) + gum_neg[M_+m];
                g_bsel[m] = (v1 > v0) ? 1 : 0;
            }
        }
    } else {
        int bb = b - 72;                 // 320 = 16 fv x (5 m-chunks x 4 e-slices)
        int fv = bb & 15, rem = bb >> 4;
        int my = rem % 5, es = rem / 5;
        int m  = my*256 + tid;
        if (m >= M_) return;
        // bs computed from inputs (no dependency on k1-half)
        float v0 = clampf(coeff_neg[m],    -1.f, 1.f) + gum_neg[m];
        float v1 = clampf(coeff_neg[M_+m], -1.f, 1.f) + gum_neg[M_+m];
        int bs = (v1 > v0) ? 1 : 0;
        float AA = 0.f, BB = 0.f;
        #pragma unroll 4
        for (int r = 0; r < 16; r++){
            int e = es*16 + r;
            float ax = (m < NIN_) ? a[(size_t)(fv*E_+e)*NIN_ + m] : ((m == NIN_) ? 1.f : 0.f);
            float an = an_of(ax, bs, m);
            AA += ax*ax;
            BB += an*an;
        }
        int f = fv >> 2;
        atomicAdd(&g_AAf[f*M_ + m], AA);
        atomicAdd(&g_BBf[f*M_ + m], BB);
    }
}

// ---------------- KSP: neg flags + pos powAB + gneg ----------------
__global__ __launch_bounds__(256) void ksp(const float* __restrict__ theta_,
                                           const float* __restrict__ fault)
{
    int f  = blockIdx.x;
    int nt = blockIdx.y;
    int mc = blockIdx.z;
    int n  = nt*128 + (threadIdx.x & 127);
    int ms = threadIdx.x >> 7;
    float ginv = 0.1f / gmin_of(n);
    int neg = 0;
    double pab = 0.0;
    #pragma unroll 3
    for (int r=0; r<57; r++){
        int m = mc*114 + r*2 + ms;
        float tc = clampf(theta_[m*N_ + n], -1.f, 1.f);
        float gi = fabsf(tc);
        float th = (gi < 0.01f) ? 0.f : tc;
        float fa = fault[(f*M_ + m)*N_ + n];
        float g  = gi * ginv;
        float s  = th*fa;
        if (s < 0.f){ neg = 1; atomicAdd(&g_gneg[f*M_ + m], g); }
        else        { pab += (double)(g * g_AAf[f*M_ + m]); }
    }
    if (neg){ atomicOr(&g_negflag[f*NT2_ + nt], 1); atomicOr(&g_anyneg, 1); }
    __shared__ double sred[256];
    sred[threadIdx.x] = pab;
    __syncthreads();
    for (int s=128; s>0; s>>=1){
        if (threadIdx.x < s) sred[threadIdx.x] += sred[threadIdx.x+s];
        __syncthreads();
    }
    if (threadIdx.x == 0) atomicAdd(&g_powAB, sred[0]);
}

// ---------------- K5: bf16 mma.sync dual GEMM, cp.async depth-2 (hot path unchanged) ----
__global__ __launch_bounds__(256, 2) void k5_mma(const float* __restrict__ a,
                                                 const float* __restrict__ theta_,
                                                 const float* __restrict__ noise,
                                                 const float* __restrict__ fault,
                                                 float* __restrict__ out)
{
    const int fv = blockIdx.x, f = fv >> 2;
    const int n0 = blockIdx.y * 64;
    const int tid = threadIdx.x;
    const int lane = tid & 31, w = tid >> 5;
    const bool anyneg = (g_negflag[f*NT2_ + (blockIdx.y >> 1)] != 0);

    __shared__ float rawTh[2][16][64], rawNo[2][16][64], rawFa[2][16][64];
    __shared__ uint16_t Wt[64][20], Gt[64][20], Wq[64][20], Gq[64][20];
    __shared__ uint16_t axs[64][20], ans[64][20];
    __shared__ float dsum_s[4][64];
    __shared__ float invd_s[64];
    __shared__ double sred[256];

    const int crow = tid >> 4;           // cp.async m-row within tile
    const int cch  = (tid & 15) * 4;     // float offset within 64-col row
    const int sn = tid & 63, kq = tid >> 6;   // W/G: col n0+sn, k = kq*4+j
    const int sk = tid & 15, se = tid >> 4;   // ax:  k = sk, e = se + 16r
    const int g = lane >> 2, t4 = lane & 3;
    const int nw = (w & 3) * 16, ec0 = (w >> 2) * 32;

    const float ginv = 0.1f / gmin_of(n0 + sn);
    float dsum = 0.f;
    float zacc[4][4], z2acc[4][4];
    #pragma unroll
    for (int c=0;c<4;c++)
        #pragma unroll
        for (int q=0;q<4;q++){ zacc[c][q]=0.f; z2acc[c][q]=0.f; }

    auto issue_tile = [&](int t, int s){
        int m = t*16 + crow;
        if (m < M_){
            CPA16(su32(&rawTh[s][crow][cch]), &theta_[(size_t)m*N_ + n0 + cch]);
            CPA16(su32(&rawNo[s][crow][cch]), &noise[((size_t)(fv*M_ + m))*N_ + n0 + cch]);
            CPA16(su32(&rawFa[s][crow][cch]), &fault[((size_t)(f*M_ + m))*N_ + n0 + cch]);
        }
    };

    issue_tile(0, 0); CPCOMMIT();
    issue_tile(1, 1); CPCOMMIT();

    float av[4], anv[4];
    {
        int m = sk;
        int bs = anyneg ? g_bsel[m] : 0;
        #pragma unroll
        for (int r=0;r<4;r++){
            av[r]  = a[(size_t)(fv*E_ + se + r*16)*NIN_ + m];
            anv[r] = anyneg ? an_of(av[r], bs, m) : 0.f;
        }
    }

    for (int t = 0; t < 65; t++){
        const int buf = t & 1;
        CPWAIT1();
        __syncthreads();
        // ---- stage W/G from raw smem (+ dsum) ----
        {
            float wv[4], gv[4]; bool pv[4];
            #pragma unroll
            for (int j=0;j<4;j++){
                int m = t*16 + kq*4 + j;
                bool vm = (m < M_);
                float thr = vm ? rawTh[buf][kq*4+j][sn] : 0.f;
                float nor = vm ? rawNo[buf][kq*4+j][sn] : 0.f;
                float far = vm ? rawFa[buf][kq*4+j][sn] : 0.f;
                float tc = clampf(thr, -1.f, 1.f);
                float gi = fabsf(tc);
                float thv = (gi < 0.01f) ? 0.f : tc;
                float gt = vm ? gi * ginv : 0.f;
                float tn = thv*(0.9f + 0.2f*nor)*far;
                wv[j] = fabsf(tn);
                gv[j] = gt;
                pv[j] = (tn >= 0.f);
                dsum += wv[j];
            }
            if (!anyneg){
                *(uint32_t*)&Wt[sn][kq*4]   = bpack(wv[0], wv[1]);
                *(uint32_t*)&Wt[sn][kq*4+2] = bpack(wv[2], wv[3]);
                *(uint32_t*)&Gt[sn][kq*4]   = bpack(gv[0], gv[1]);
                *(uint32_t*)&Gt[sn][kq*4+2] = bpack(gv[2], gv[3]);
            } else {
                *(uint32_t*)&Wt[sn][kq*4]   = bpack(pv[0]?wv[0]:0.f, pv[1]?wv[1]:0.f);
                *(uint32_t*)&Wt[sn][kq*4+2] = bpack(pv[2]?wv[2]:0.f, pv[3]?wv[3]:0.f);
                *(uint32_t*)&Wq[sn][kq*4]   = bpack(pv[0]?0.f:wv[0], pv[1]?0.f:wv[1]);
                *(uint32_t*)&Wq[sn][kq*4+2] = bpack(pv[2]?0.f:wv[2], pv[3]?0.f:wv[3]);
                *(uint32_t*)&Gt[sn][kq*4]   = bpack(pv[0]?gv[0]:0.f, pv[1]?gv[1]:0.f);
                *(uint32_t*)&Gt[sn][kq*4+2] = bpack(pv[2]?gv[2]:0.f, pv[3]?gv[3]:0.f);
                *(uint32_t*)&Gq[sn][kq*4]   = bpack(pv[0]?0.f:gv[0], pv[1]?0.f:gv[1]);
                *(uint32_t*)&Gq[sn][kq*4+2] = bpack(pv[2]?0.f:gv[2], pv[3]?0.f:gv[3]);
            }
            #pragma unroll
            for (int r=0;r<4;r++){
                axs[se + r*16][sk] = b1(av[r]);
                if (anyneg) ans[se + r*16][sk] = b1(anv[r]);
            }
        }
        // ---- prefetch a regs for t+1 ----
        if (t < 64){
            int m = (t+1)*16 + sk;
            int bs = (anyneg && m < M_) ? g_bsel[m] : 0;
            #pragma unroll
            for (int r=0;r<4;r++){
                av[r] = (m < NIN_) ? a[(size_t)(fv*E_ + se + r*16)*NIN_ + m]
                                   : ((m == NIN_) ? 1.f : 0.f);
                if (anyneg) anv[r] = (m < M_) ? an_of(av[r], bs, m) : 0.f;
            }
        }
        __syncthreads();
        // ---- issue raw tile t+2 ----
        if (t + 2 < 65) issue_tile(t + 2, buf);
        CPCOMMIT();
        // ---- mma ----
        {
            uint32_t aw0 = *(const uint32_t*)&Wt[nw+g  ][2*t4];
            uint32_t aw1 = *(const uint32_t*)&Wt[nw+g+8][2*t4];
            uint32_t aw2 = *(const uint32_t*)&Wt[nw+g  ][2*t4+8];
            uint32_t aw3 = *(const uint32_t*)&Wt[nw+g+8][2*t4+8];
            uint32_t ag0 = *(const uint32_t*)&Gt[nw+g  ][2*t4];
            uint32_t ag1 = *(const uint32_t*)&Gt[nw+g+8][2*t4];
            uint32_t ag2 = *(const uint32_t*)&Gt[nw+g  ][2*t4+8];
            uint32_t ag3 = *(const uint32_t*)&Gt[nw+g+8][2*t4+8];
            #pragma unroll
            for (int c=0;c<4;c++){
                int e = ec0 + c*8 + g;
                uint32_t b0  = *(const uint32_t*)&axs[e][2*t4];
                uint32_t bb1 = *(const uint32_t*)&axs[e][2*t4+8];
                mma_bf16(zacc[c],  aw0, aw1, aw2, aw3, b0, bb1);
                mma_bf16(z2acc[c], ag0, ag1, ag2, ag3, b0, bb1);
            }
            if (anyneg){
                uint32_t q0 = *(const uint32_t*)&Wq[nw+g  ][2*t4];
                uint32_t q1 = *(const uint32_t*)&Wq[nw+g+8][2*t4];
                uint32_t q2 = *(const uint32_t*)&Wq[nw+g  ][2*t4+8];
                uint32_t q3 = *(const uint32_t*)&Wq[nw+g+8][2*t4+8];
                uint32_t h0 = *(const uint32_t*)&Gq[nw+g  ][2*t4];
                uint32_t h1 = *(const uint32_t*)&Gq[nw+g+8][2*t4];
                uint32_t h2 = *(const uint32_t*)&Gq[nw+g  ][2*t4+8];
                uint32_t h3 = *(const uint32_t*)&Gq[nw+g+8][2*t4+8];
                #pragma unroll
                for (int c=0;c<4;c++){
                    int e = ec0 + c*8 + g;
                    uint32_t b0  = *(const uint32_t*)&ans[e][2*t4];
                    uint32_t bb1 = *(const uint32_t*)&ans[e][2*t4+8];
                    mma_bf16(zacc[c],  q0, q1, q2, q3, b0, bb1);
                    mma_bf16(z2acc[c], h0, h1, h2, h3, b0, bb1);
                }
            }
        }
    }

    // ---- D reduction ----
    dsum_s[kq][sn] = dsum;
    __syncthreads();
    if (tid < 64)
        invd_s[tid] = 1.f/(dsum_s[0][tid]+dsum_s[1][tid]+dsum_s[2][tid]+dsum_s[3][tid] + 1e-10f);
    __syncthreads();

    // ---- epilogue ----
    const int r0 = nw + g, r1 = nw + g + 8;
    const float invd0 = invd_s[r0], invd1 = invd_s[r1];
    const float gs0 = g_sumabs[n0+r0] * (0.1f / gmin_of(n0+r0));
    const float gs1 = g_sumabs[n0+r1] * (0.1f / gmin_of(n0+r1));
    const int as0 = g_actsel[n0+r0], as1 = g_actsel[n0+r1];
    double cp = 0.0;
    #pragma unroll
    for (int c=0;c<4;c++){
        int e0 = ec0 + c*8 + 2*t4;
        float vals[4] = { zacc[c][0], zacc[c][1], zacc[c][2], zacc[c][3] };
        float v2[4]   = { z2acc[c][0], z2acc[c][1], z2acc[c][2], z2acc[c][3] };
        #pragma unroll
        for (int q=0;q<4;q++){
            int e  = e0 + (q & 1);
            int rr = (q < 2) ? r0 : r1;
            float invd = (q < 2) ? invd0 : invd1;
            float gsn  = (q < 2) ? gs0 : gs1;
            int   asel = (q < 2) ? as0 : as1;
            float zz = vals[q] * invd;
            float act = asel ? tanhf(zz) : (1.f/(1.f + expf(2.f - 4.f*zz)));
            out[(size_t)(fv*E_ + e)*N_ + n0 + rr] = act;
            cp += (double)zz * ((double)gsn*(double)zz - 2.0*(double)v2[q]);
        }
    }
    sred[tid] = cp;
    __syncthreads();
    for (int s=128; s>0; s>>=1){
        if (tid < s) sred[tid] += sred[tid+s];
        __syncthreads();
    }
    if (tid == 0) atomicAdd(&g_cross, sred[0]);
}

// ---------------- K6: neg powAB + finalize + reset state for next call ----------------
__global__ void k6_fin(float* __restrict__ out)
{
    int tid = threadIdx.x;
    if (blockIdx.x == 0){
        __shared__ double sred[256];
        double s = 0.0;
        if (g_anyneg){
            for (int i = tid; i < F_*M_; i += 256)
                s += (double)g_gneg[i] * (double)g_BBf[i];
        }
        sred[tid] = s;
        __syncthreads();
        for (int st=128; st>0; st>>=1){
            if (tid < st) sred[tid] += sred[tid+st];
            __syncthreads();
        }
        if (tid == 0)
            out[(size_t)FV_*E_*N_] = (float)((g_powAB + g_cross + sred[0]) * (1.0/1024.0));
        __syncthreads();
        for (int i = tid; i < F_*M_; i += 256){ g_gneg[i] = 0.f; g_BBf[i] = 0.f; }
        if (tid == 0){ g_powAB = 0.0; g_cross = 0.0; g_anyneg = 0; }
    } else {
        int base = (blockIdx.x - 1)*256 + tid;   // blocks 1..17 -> 0..4351
        if (base < N_){ g_gmax_not[base] = 0u; g_sumabs[base] = 0.f; }
        if (base < F_*M_) g_AAf[base] = 0.f;
        if (base < F_*NT2_) g_negflag[base] = 0;
    }
}

// ---------------- launch ----------------
extern "C" void kernel_launch(void* const* d_in, const int* in_sizes, int n_in,
                              void* d_out, int out_size)
{
    const float* a         = (const float*)d_in[0];
    const float* theta_    = (const float*)d_in[1];
    const float* coeff_act = (const float*)d_in[2];
    const float* coeff_neg = (const float*)d_in[3];
    const float* noise_u   = (const float*)d_in[4];
    const float* gum_act   = (const float*)d_in[5];
    const float* gum_neg   = (const float*)d_in[6];
    const float* fault     = (const float*)d_in[7];
    float* out = (float*)d_out;

    kprep <<<392, 256>>>(theta_, coeff_act, coeff_neg, gum_act, gum_neg, a);
    ksp   <<<dim3(F_,NT2_,9),256>>>(theta_, fault);
    k5_mma<<<dim3(FV_,NT_), 256>>>(a, theta_, noise_u, fault, out);
    k6_fin<<<18, 256>>>(out);
}